// round 1
// baseline (speedup 1.0000x reference)
#include <cuda_runtime.h>

// Problem dims (fixed by the dataset)
#define BB 4
#define SS 2048
#define HH 1024
#define LL 4
#define FF 4096
#define NN (BB*SS)          // 8192 token rows
#define NCHUNK 32
#define CLEN (SS/NCHUNK)    // 64

// ---------------- scratch (no allocations allowed) ----------------
__device__ float g_h  [(size_t)NN*HH];
__device__ float g_tre[(size_t)NN*HH];
__device__ float g_tim[(size_t)NN*HH];
__device__ float g_y  [(size_t)NN*HH];
__device__ float g_f  [(size_t)NN*FF];
__device__ float2 g_carry[BB*NCHUNK*HH];

// ---------------- embedding ----------------
__global__ void embed_kernel(const int* __restrict__ ids, const float* __restrict__ we,
                             const float* __restrict__ pe, float* __restrict__ out)
{
    int e = blockIdx.x * blockDim.x + threadIdx.x;   // one float4 per thread
    int n  = e >> 8;                                  // HH/4 = 256 quads per row
    int hq = (e & 255) << 2;
    int s  = n & (SS - 1);
    int id = ids[n];
    float4 w = *(const float4*)(we + (size_t)id * HH + hq);
    float4 p = *(const float4*)(pe + (size_t)s  * HH + hq);
    *(float4*)(out + (size_t)n * HH + hq) =
        make_float4(w.x + p.x, w.y + p.y, w.z + p.z, w.w + p.w);
}

// ---------------- GEMM 1: Bu_re/Bu_im = (h @ B^T) * gamma ----------------
// A[N,K] row-major, W[M,K] row-major (NT). dual output with shared A tile.
__global__ __launch_bounds__(256) void gemm_bu(
    const float* __restrict__ A, const float* __restrict__ WRe, const float* __restrict__ WIm,
    const float* __restrict__ nul,
    float* __restrict__ ORe, float* __restrict__ OIm, int M, int K)
{
    __shared__ __align__(16) float As[16*68], Wr[16*68], Wi[16*68];
    const int tid = threadIdx.x;
    const int tx = tid & 15, ty = tid >> 4;
    const int n0 = blockIdx.y << 6, m0 = blockIdx.x << 6;
    const int lr = tid >> 2;
    const int lk = (tid & 3) << 2;
    const float* Ap  = A   + (size_t)(n0 + lr) * K + lk;
    const float* Wrp = WRe + (size_t)(m0 + lr) * K + lk;
    const float* Wip = WIm + (size_t)(m0 + lr) * K + lk;
    float aR[4][4] = {}, aI[4][4] = {};
    for (int k0 = 0; k0 < K; k0 += 16) {
        float4 a  = *(const float4*)(Ap  + k0);
        float4 wr = *(const float4*)(Wrp + k0);
        float4 wi = *(const float4*)(Wip + k0);
        __syncthreads();
        As[(lk+0)*68+lr]=a.x;  As[(lk+1)*68+lr]=a.y;  As[(lk+2)*68+lr]=a.z;  As[(lk+3)*68+lr]=a.w;
        Wr[(lk+0)*68+lr]=wr.x; Wr[(lk+1)*68+lr]=wr.y; Wr[(lk+2)*68+lr]=wr.z; Wr[(lk+3)*68+lr]=wr.w;
        Wi[(lk+0)*68+lr]=wi.x; Wi[(lk+1)*68+lr]=wi.y; Wi[(lk+2)*68+lr]=wi.z; Wi[(lk+3)*68+lr]=wi.w;
        __syncthreads();
        #pragma unroll
        for (int kk = 0; kk < 16; kk++) {
            float4 av  = *(const float4*)&As[kk*68 + (ty<<2)];
            float4 wrv = *(const float4*)&Wr[kk*68 + (tx<<2)];
            float4 wiv = *(const float4*)&Wi[kk*68 + (tx<<2)];
            float avv[4] = {av.x, av.y, av.z, av.w};
            float wr4[4] = {wrv.x, wrv.y, wrv.z, wrv.w};
            float wi4[4] = {wiv.x, wiv.y, wiv.z, wiv.w};
            #pragma unroll
            for (int i = 0; i < 4; i++)
                #pragma unroll
                for (int j = 0; j < 4; j++) {
                    aR[i][j] = fmaf(avv[i], wr4[j], aR[i][j]);
                    aI[i][j] = fmaf(avv[i], wi4[j], aI[i][j]);
                }
        }
    }
    float gma[4];
    #pragma unroll
    for (int j = 0; j < 4; j++) {
        int u = m0 + (tx<<2) + j;
        gma[j] = sqrtf(fmaxf(1.f - expf(-2.f * expf(nul[u])), 0.f));
    }
    #pragma unroll
    for (int i = 0; i < 4; i++) {
        size_t o = (size_t)(n0 + (ty<<2) + i) * M + m0 + (tx<<2);
        *(float4*)(ORe + o) = make_float4(aR[i][0]*gma[0], aR[i][1]*gma[1], aR[i][2]*gma[2], aR[i][3]*gma[3]);
        *(float4*)(OIm + o) = make_float4(aI[i][0]*gma[0], aI[i][1]*gma[1], aI[i][2]*gma[2], aI[i][3]*gma[3]);
    }
}

// ---------------- GEMM 2: y = re @ C_re^T - im @ C_im^T ----------------
__global__ __launch_bounds__(256) void gemm_y(
    const float* __restrict__ ARe, const float* __restrict__ AIm,
    const float* __restrict__ WRe, const float* __restrict__ WIm,
    float* __restrict__ O, int M, int K)
{
    __shared__ __align__(16) float Ar[16*68], Ai[16*68], Wr[16*68], Wi[16*68];
    const int tid = threadIdx.x;
    const int tx = tid & 15, ty = tid >> 4;
    const int n0 = blockIdx.y << 6, m0 = blockIdx.x << 6;
    const int lr = tid >> 2;
    const int lk = (tid & 3) << 2;
    const float* Arp = ARe + (size_t)(n0 + lr) * K + lk;
    const float* Aip = AIm + (size_t)(n0 + lr) * K + lk;
    const float* Wrp = WRe + (size_t)(m0 + lr) * K + lk;
    const float* Wip = WIm + (size_t)(m0 + lr) * K + lk;
    float acc[4][4] = {};
    for (int k0 = 0; k0 < K; k0 += 16) {
        float4 ar = *(const float4*)(Arp + k0);
        float4 ai = *(const float4*)(Aip + k0);
        float4 wr = *(const float4*)(Wrp + k0);
        float4 wi = *(const float4*)(Wip + k0);
        __syncthreads();
        Ar[(lk+0)*68+lr]=ar.x; Ar[(lk+1)*68+lr]=ar.y; Ar[(lk+2)*68+lr]=ar.z; Ar[(lk+3)*68+lr]=ar.w;
        Ai[(lk+0)*68+lr]=ai.x; Ai[(lk+1)*68+lr]=ai.y; Ai[(lk+2)*68+lr]=ai.z; Ai[(lk+3)*68+lr]=ai.w;
        Wr[(lk+0)*68+lr]=wr.x; Wr[(lk+1)*68+lr]=wr.y; Wr[(lk+2)*68+lr]=wr.z; Wr[(lk+3)*68+lr]=wr.w;
        Wi[(lk+0)*68+lr]=wi.x; Wi[(lk+1)*68+lr]=wi.y; Wi[(lk+2)*68+lr]=wi.z; Wi[(lk+3)*68+lr]=wi.w;
        __syncthreads();
        #pragma unroll
        for (int kk = 0; kk < 16; kk++) {
            float4 arv = *(const float4*)&Ar[kk*68 + (ty<<2)];
            float4 aiv = *(const float4*)&Ai[kk*68 + (ty<<2)];
            float4 wrv = *(const float4*)&Wr[kk*68 + (tx<<2)];
            float4 wiv = *(const float4*)&Wi[kk*68 + (tx<<2)];
            float arr[4] = {arv.x, arv.y, arv.z, arv.w};
            float aii[4] = {-aiv.x, -aiv.y, -aiv.z, -aiv.w};
            float wr4[4] = {wrv.x, wrv.y, wrv.z, wrv.w};
            float wi4[4] = {wiv.x, wiv.y, wiv.z, wiv.w};
            #pragma unroll
            for (int i = 0; i < 4; i++)
                #pragma unroll
                for (int j = 0; j < 4; j++) {
                    acc[i][j] = fmaf(arr[i], wr4[j], acc[i][j]);
                    acc[i][j] = fmaf(aii[i], wi4[j], acc[i][j]);
                }
        }
    }
    #pragma unroll
    for (int i = 0; i < 4; i++) {
        size_t o = (size_t)(n0 + (ty<<2) + i) * M + m0 + (tx<<2);
        *(float4*)(O + o) = make_float4(acc[i][0], acc[i][1], acc[i][2], acc[i][3]);
    }
}

// ---------------- GEMM 3/4: out = A @ W^T + bias, optional exact GELU ----------------
__global__ __launch_bounds__(256) void gemm_bias(
    const float* __restrict__ A, const float* __restrict__ W,
    const float* __restrict__ bias, float* __restrict__ O,
    int M, int K, int do_gelu)
{
    __shared__ __align__(16) float As[16*68], Ws[16*68];
    const int tid = threadIdx.x;
    const int tx = tid & 15, ty = tid >> 4;
    const int n0 = blockIdx.y << 6, m0 = blockIdx.x << 6;
    const int lr = tid >> 2;
    const int lk = (tid & 3) << 2;
    const float* Ap = A + (size_t)(n0 + lr) * K + lk;
    const float* Wp = W + (size_t)(m0 + lr) * K + lk;
    float acc[4][4] = {};
    for (int k0 = 0; k0 < K; k0 += 16) {
        float4 a = *(const float4*)(Ap + k0);
        float4 w = *(const float4*)(Wp + k0);
        __syncthreads();
        As[(lk+0)*68+lr]=a.x; As[(lk+1)*68+lr]=a.y; As[(lk+2)*68+lr]=a.z; As[(lk+3)*68+lr]=a.w;
        Ws[(lk+0)*68+lr]=w.x; Ws[(lk+1)*68+lr]=w.y; Ws[(lk+2)*68+lr]=w.z; Ws[(lk+3)*68+lr]=w.w;
        __syncthreads();
        #pragma unroll
        for (int kk = 0; kk < 16; kk++) {
            float4 av = *(const float4*)&As[kk*68 + (ty<<2)];
            float4 wv = *(const float4*)&Ws[kk*68 + (tx<<2)];
            float avv[4] = {av.x, av.y, av.z, av.w};
            float wvv[4] = {wv.x, wv.y, wv.z, wv.w};
            #pragma unroll
            for (int i = 0; i < 4; i++)
                #pragma unroll
                for (int j = 0; j < 4; j++)
                    acc[i][j] = fmaf(avv[i], wvv[j], acc[i][j]);
        }
    }
    float bv[4];
    #pragma unroll
    for (int j = 0; j < 4; j++) bv[j] = bias[m0 + (tx<<2) + j];
    #pragma unroll
    for (int i = 0; i < 4; i++) {
        float v[4];
        #pragma unroll
        for (int j = 0; j < 4; j++) {
            v[j] = acc[i][j] + bv[j];
            if (do_gelu) v[j] = v[j] * normcdff(v[j]);   // exact GELU: x * Phi(x)
        }
        size_t o = (size_t)(n0 + (ty<<2) + i) * M + m0 + (tx<<2);
        *(float4*)(O + o) = make_float4(v[0], v[1], v[2], v[3]);
    }
}

// ---------------- chunked complex scan: state_s = lam*state_{s-1} + x_s ----------------
__device__ __forceinline__ void lam_of(const float* nul, const float* thl, int u,
                                       float& lre, float& lim)
{
    float r   = expf(-expf(nul[u]));
    float ang = expf(thl[u]);
    lre = r * cosf(ang);
    lim = r * sinf(ang);
}

__global__ void scan_pass1(const float* __restrict__ nul, const float* __restrict__ thl,
                           float* __restrict__ tre, float* __restrict__ tim,
                           float2* __restrict__ carry)
{
    int t = blockIdx.x * blockDim.x + threadIdx.x;   // BB*NCHUNK*HH threads
    int u = t & (HH - 1);
    int rest = t >> 10;
    int c = rest & (NCHUNK - 1);
    int b = rest >> 5;
    float lre, lim; lam_of(nul, thl, u, lre, lim);
    size_t base = ((size_t)b * SS + (size_t)c * CLEN) * HH + u;
    float sre = 0.f, sim = 0.f;
    #pragma unroll 4
    for (int i = 0; i < CLEN; i++) {
        size_t ix = base + (size_t)i * HH;
        float xr = tre[ix], xi = tim[ix];
        float nr = fmaf(lre, sre, fmaf(-lim, sim, xr));
        float ni = fmaf(lre, sim, fmaf( lim, sre, xi));
        sre = nr; sim = ni;
        tre[ix] = sre; tim[ix] = sim;
    }
    carry[(b * NCHUNK + c) * HH + u] = make_float2(sre, sim);
}

__global__ void scan_pass2(const float* __restrict__ nul, const float* __restrict__ thl,
                           float2* __restrict__ carry)
{
    int t = blockIdx.x * blockDim.x + threadIdx.x;   // BB*HH threads
    int u = t & (HH - 1);
    int b = t >> 10;
    float lre, lim; lam_of(nul, thl, u, lre, lim);
    float pr = 1.f, pi = 0.f;                        // lam^CLEN
    #pragma unroll
    for (int i = 0; i < CLEN; i++) {
        float nr = pr * lre - pi * lim;
        float ni = pr * lim + pi * lre;
        pr = nr; pi = ni;
    }
    float cre = 0.f, cim = 0.f;                      // exclusive chunk carry
    for (int c = 0; c < NCHUNK; c++) {
        int ix = (b * NCHUNK + c) * HH + u;
        float2 f = carry[ix];
        carry[ix] = make_float2(cre, cim);
        float nr = fmaf(pr, cre, fmaf(-pi, cim, f.x));
        float ni = fmaf(pr, cim, fmaf( pi, cre, f.y));
        cre = nr; cim = ni;
    }
}

__global__ void scan_pass3(const float* __restrict__ nul, const float* __restrict__ thl,
                           float* __restrict__ tre, float* __restrict__ tim,
                           const float2* __restrict__ carry)
{
    int t = blockIdx.x * blockDim.x + threadIdx.x;
    int u = t & (HH - 1);
    int rest = t >> 10;
    int c = rest & (NCHUNK - 1);
    int b = rest >> 5;
    float2 cc = carry[(b * NCHUNK + c) * HH + u];
    if (cc.x == 0.f && cc.y == 0.f) return;          // chunk 0 (and dead chains)
    float lre, lim; lam_of(nul, thl, u, lre, lim);
    size_t base = ((size_t)b * SS + (size_t)c * CLEN) * HH + u;
    float pr = lre, pi = lim;                         // lam^(i+1)
    #pragma unroll 4
    for (int i = 0; i < CLEN; i++) {
        size_t ix = base + (size_t)i * HH;
        float ar = fmaf(pr, cc.x, fmaf(-pi, cc.y, tre[ix]));
        float ai = fmaf(pr, cc.y, fmaf( pi, cc.x, tim[ix]));
        tre[ix] = ar; tim[ix] = ai;
        float nr = pr * lre - pi * lim;
        float ni = pr * lim + pi * lre;
        pr = nr; pi = ni;
    }
}

// ---------------- fused residual + RMS-LN (+ optional D*h term) ----------------
// z = h*(1+D) + y   (D==null -> z = h + y);  out = z * rsqrt(mean(z^2)+1e-12) + bias
__global__ void ln_kernel(const float* __restrict__ h, const float* __restrict__ y,
                          const float* __restrict__ Dl, const float* __restrict__ bias,
                          float* __restrict__ out)
{
    int n = blockIdx.x;
    int t = threadIdx.x;                 // 256 threads, 4 elems each
    size_t idx = (size_t)n * HH + (t << 2);
    float4 hv = *(const float4*)(h + idx);
    float4 yv = *(const float4*)(y + idx);
    float4 z;
    if (Dl) {
        float4 dv = *(const float4*)(Dl + (t << 2));
        z.x = fmaf(hv.x, 1.f + dv.x, yv.x);
        z.y = fmaf(hv.y, 1.f + dv.y, yv.y);
        z.z = fmaf(hv.z, 1.f + dv.z, yv.z);
        z.w = fmaf(hv.w, 1.f + dv.w, yv.w);
    } else {
        z.x = hv.x + yv.x; z.y = hv.y + yv.y; z.z = hv.z + yv.z; z.w = hv.w + yv.w;
    }
    float s = z.x*z.x + z.y*z.y + z.z*z.z + z.w*z.w;
    #pragma unroll
    for (int o = 16; o; o >>= 1) s += __shfl_xor_sync(0xffffffffu, s, o);
    __shared__ float red[8];
    if ((t & 31) == 0) red[t >> 5] = s;
    __syncthreads();
    float tot = red[0]+red[1]+red[2]+red[3]+red[4]+red[5]+red[6]+red[7];
    float inv = rsqrtf(tot * (1.f / (float)HH) + 1e-12f);
    float4 bv = *(const float4*)(bias + (t << 2));
    float4 o4 = make_float4(fmaf(z.x, inv, bv.x), fmaf(z.y, inv, bv.y),
                            fmaf(z.z, inv, bv.z), fmaf(z.w, inv, bv.w));
    *(float4*)(out + idx) = o4;
}

// ---------------- launch ----------------
extern "C" void kernel_launch(void* const* d_in, const int* in_sizes, int n_in,
                              void* d_out, int out_size)
{
    const int*   ids = (const int*)  d_in[0];
    const float* we  = (const float*)d_in[1];
    const float* pe  = (const float*)d_in[2];
    const float* nu  = (const float*)d_in[3];
    const float* th  = (const float*)d_in[4];
    const float* Bre = (const float*)d_in[5];
    const float* Bim = (const float*)d_in[6];
    const float* Cre = (const float*)d_in[7];
    const float* Cim = (const float*)d_in[8];
    const float* Dp  = (const float*)d_in[9];
    const float* rnb = (const float*)d_in[10];
    const float* w1  = (const float*)d_in[11];
    const float* b1  = (const float*)d_in[12];
    const float* w2  = (const float*)d_in[13];
    const float* b2  = (const float*)d_in[14];
    const float* fnb = (const float*)d_in[15];
    float* out = (float*)d_out;

    float *ph, *ptre, *ptim, *py, *pf; float2* pc;
    cudaGetSymbolAddress((void**)&ph,   g_h);
    cudaGetSymbolAddress((void**)&ptre, g_tre);
    cudaGetSymbolAddress((void**)&ptim, g_tim);
    cudaGetSymbolAddress((void**)&py,   g_y);
    cudaGetSymbolAddress((void**)&pf,   g_f);
    cudaGetSymbolAddress((void**)&pc,   g_carry);

    embed_kernel<<<(size_t)NN*HH/4/256, 256>>>(ids, we, pe, ph);

    for (int l = 0; l < LL; l++) {
        const float* nul = nu + l*HH;
        const float* thl = th + l*HH;

        gemm_bu<<<dim3(HH/64, NN/64), 256>>>(ph, Bre + (size_t)l*HH*HH, Bim + (size_t)l*HH*HH,
                                             nul, ptre, ptim, HH, HH);
        scan_pass1<<<BB*NCHUNK*HH/256, 256>>>(nul, thl, ptre, ptim, pc);
        scan_pass2<<<BB*HH/256, 256>>>(nul, thl, pc);
        scan_pass3<<<BB*NCHUNK*HH/256, 256>>>(nul, thl, ptre, ptim, pc);
        gemm_y<<<dim3(HH/64, NN/64), 256>>>(ptre, ptim, Cre + (size_t)l*HH*HH, Cim + (size_t)l*HH*HH,
                                            py, HH, HH);
        ln_kernel<<<NN, 256>>>(ph, py, Dp + l*HH, rnb + l*HH, ph);

        gemm_bias<<<dim3(FF/64, NN/64), 256>>>(ph, w1 + (size_t)l*FF*HH, b1 + l*FF, pf, FF, HH, 1);
        gemm_bias<<<dim3(HH/64, NN/64), 256>>>(pf, w2 + (size_t)l*HH*FF, b2 + l*HH, py, HH, FF, 0);

        float* lnout = (l == LL-1) ? out : ph;
        ln_kernel<<<NN, 256>>>(ph, py, nullptr, fnb + l*HH, lnout);
    }
}